// round 12
// baseline (speedup 1.0000x reference)
#include <cuda_runtime.h>
#include <cuda_fp16.h>

#define N_NODES 50000
#define T_STEPS 8
#define E_EDGES 800000
#define XD 128
#define HD 64
#define ZD 32
#define CAP 96        // Poisson(16) tail beyond 96 ~ e^-80
#define WPITCH 68     // transposed-W2 smem pitch (68 mod 32 = 4 -> conflict-free LDS.128)

#define NPG 4         // nodes per warp in gemm role
#define NB_L1 6250    // gather role: 50000 nodes / 8 warps
#define NB_GEM 1563   // gemm role: 50000 / (8 warps * 4 nodes)
#define NB_L2 6250    // layer2 role: 50000 / 8 warps
#define NB_BIN 3125   // bin role: 800000 edges / 256
#define NB_DNV 196    // dinv role: 50000 / 256

// ---- scratch (no allocations allowed) ----
__device__ __half g_xW1[N_NODES * HD];                      // x @ W1, fp16 (6.4 MB)
__device__ float  g_h[2][N_NODES * HD];                     // relu(agg+b1), double-buffered
__device__ float  g_z[2][N_NODES * ZD];                     // h @ W2, double-buffered
__device__ unsigned long long g_pack[T_STEPS * N_NODES];    // (count<<52)|fixed32(sum w)
__device__ float  g_dinv[T_STEPS * N_NODES];
__device__ int    g_count[T_STEPS * N_NODES];
__device__ int2   g_bins[(size_t)T_STEPS * N_NODES * CAP];  // (src, bits(w|nrm)) (307 MB)

// ============================================================
// Setup: g_xW1 = x @ W1   (warp per node, W1 in shared) -> fp16
// ============================================================
__global__ void k_xw1(const float* __restrict__ x, const float* __restrict__ W1) {
    __shared__ float sW[XD * HD];
    for (int i = threadIdx.x; i < XD * HD; i += blockDim.x) sW[i] = W1[i];
    __syncthreads();

    int node = blockIdx.x * (blockDim.x >> 5) + (threadIdx.x >> 5);
    int lane = threadIdx.x & 31;
    if (node >= N_NODES) return;

    const float* xr = x + node * XD;
    float xv[4];
    xv[0] = xr[lane];
    xv[1] = xr[lane + 32];
    xv[2] = xr[lane + 64];
    xv[3] = xr[lane + 96];

    float a0 = 0.f, a1 = 0.f;
#pragma unroll
    for (int q = 0; q < 4; q++) {
#pragma unroll
        for (int k = 0; k < 32; k++) {
            float xk = __shfl_sync(0xffffffffu, xv[q], k);
            int kk = q * 32 + k;
            a0 = fmaf(xk, sW[kk * HD + lane], a0);
            a1 = fmaf(xk, sW[kk * HD + lane + 32], a1);
        }
    }
    g_xW1[node * HD + lane]      = __float2half(a0);
    g_xW1[node * HD + lane + 32] = __float2half(a1);
}

// ============================================================
// Work bodies
// ============================================================
__global__ void k_init() {
    int i = blockIdx.x * blockDim.x + threadIdx.x;
    if (i < T_STEPS * N_NODES) g_pack[i] = 0ull;
}

__device__ __forceinline__ void bin_work(int t, int e, const int* __restrict__ ei,
                                         const float* __restrict__ ew) {
    const int* src = ei + (size_t)t * 2 * E_EDGES;
    const int* dst = src + E_EDGES;
    int s = src[e];
    int d = dst[e];
    float w = ew[(size_t)t * E_EDGES + e];
    int base = t * N_NODES + d;
    unsigned long long add =
        (1ull << 52) | (unsigned long long)(w * 4294967296.0f);
    unsigned long long old = atomicAdd(&g_pack[base], add);
    int p = (int)(old >> 52);
    if (p < CAP) g_bins[(size_t)base * CAP + p] = make_int2(s, __float_as_int(w));
}

__device__ __forceinline__ void dinv_work(int i) {
    unsigned long long v = g_pack[i];
    g_count[i] = (int)(v >> 52);
    float deg = 1.0f + (float)(v & ((1ull << 52) - 1ull)) * (1.0f / 4294967296.0f);
    g_dinv[i] = rsqrtf(deg);
}

// gather1: R10-exact gather; h -> g_h[t&1] (no GEMM tail)
__device__ __forceinline__ void gather1_work(const float* __restrict__ b1, int t,
                                             float* __restrict__ hbuf,
                                             int node, int lane) {
    int base = t * N_NODES + node;
    float dv = g_dinv[base];
    int   c  = min(g_count[base], CAP);
    const float* dinv_t = g_dinv + t * N_NODES;
    int2* bp = g_bins + (size_t)base * CAP;

    int   sj[3];
    float nj[3];
#pragma unroll
    for (int r = 0; r < 3; r++) {
        int j = lane + 32 * r;
        sj[r] = 0; nj[r] = 0.f;
        if (j < c) {
            int2 ent = bp[j];
            int s = ent.x;
            float nrm = dinv_t[s] * __int_as_float(ent.y) * dv;
            sj[r] = s;
            nj[r] = nrm;
            bp[j].y = __float_as_int(nrm);  // layer 2 reuses nrm
        }
    }

    const __half2* xw = reinterpret_cast<const __half2*>(g_xW1);

    float2 me = __half22float2(xw[node * 32 + lane]);   // self-loop, norm = dv*dv
    float accx = me.x * (dv * dv);
    float accy = me.y * (dv * dv);

#pragma unroll
    for (int r = 0; r < 3; r++) {
        int cnt = min(max(c - 32 * r, 0), 32);
#pragma unroll 8
        for (int k = 0; k < cnt; k++) {
            int   s   = __shfl_sync(0xffffffffu, sj[r], k);
            float nrm = __shfl_sync(0xffffffffu, nj[r], k);
            float2 v = __half22float2(xw[s * 32 + lane]);  // 128B coalesced row
            accx = fmaf(v.x, nrm, accx);
            accy = fmaf(v.y, nrm, accy);
        }
    }

    float2 bb = reinterpret_cast<const float2*>(b1)[lane];
    float h0 = fmaxf(accx + bb.x, 0.0f);
    float h1 = fmaxf(accy + bb.y, 0.0f);
    reinterpret_cast<float2*>(hbuf + node * HD)[lane] = make_float2(h0, h1);
}

// layer2: gather(g_z fp32) + b2 + tanh -> out_t  (R10-exact; bins hold nrm)
__device__ __forceinline__ void layer2_work(const float* __restrict__ b2,
                                            const float* __restrict__ zbuf,
                                            float* __restrict__ out_t, int t,
                                            int node, int lane) {
    int base = t * N_NODES + node;
    float dv = g_dinv[base];
    int   c  = min(g_count[base], CAP);
    const int2* bp = g_bins + (size_t)base * CAP;

    int   sj[3];
    float nj[3];
#pragma unroll
    for (int r = 0; r < 3; r++) {
        int j = lane + 32 * r;
        sj[r] = 0; nj[r] = 0.f;
        if (j < c) {
            int2 ent = bp[j];
            sj[r] = ent.x;
            nj[r] = __int_as_float(ent.y);  // nrm
        }
    }

    float acc = zbuf[node * ZD + lane] * (dv * dv);

#pragma unroll
    for (int r = 0; r < 3; r++) {
        int cnt = min(max(c - 32 * r, 0), 32);
#pragma unroll 8
        for (int k = 0; k < cnt; k++) {
            int   s   = __shfl_sync(0xffffffffu, sj[r], k);
            float nrm = __shfl_sync(0xffffffffu, nj[r], k);
            acc = fmaf(zbuf[s * ZD + lane], nrm, acc);
        }
    }
    out_t[node * ZD + lane] = tanhf(acc + b2[lane]);
}

// ============================================================
// 3-stage pipelined step kernel. Roles by blockIdx.x range:
//   [0, NB_L1)        gather1(t)     (if t < T)
//   [+NB_GEM)         gemm(t-1)      (if 1 <= t <= T)
//   [+NB_L2)          layer2(t-2)    (if t >= 2)
//   [+NB_BIN)         bin(t+2)       (if t+2 < T)
//   [+NB_DNV)         dinv(t+1)      (if t+1 < T)
// ============================================================
__global__ void k_step(const float* __restrict__ b1, const float* __restrict__ W2,
                       const float* __restrict__ b2,
                       float* __restrict__ out_l2, int t,
                       const int* __restrict__ ei, const float* __restrict__ ew) {
    int bx = blockIdx.x;
    int lane = threadIdx.x & 31;
    int wid  = threadIdx.x >> 5;

    if (bx < NB_L1) {
        if (t >= T_STEPS) return;
        int node = bx * 8 + wid;
        if (node >= N_NODES) return;
        gather1_work(b1, t, g_h[t & 1], node, lane);
    } else if (bx < NB_L1 + NB_GEM) {
        int tg = t - 1;
        if (tg < 0 || tg >= T_STEPS) return;
        __shared__ float sWT[ZD * WPITCH];   // transposed padded W2 (8.7 KB)
        __shared__ float sHG[8][NPG * HD];   // per-warp h rows (8 KB)
        for (int i = threadIdx.x; i < ZD * HD; i += blockDim.x) {
            int col = i >> 6, k = i & 63;
            sWT[col * WPITCH + k] = W2[k * ZD + col];
        }
        __syncthreads();

        int node0 = ((bx - NB_L1) * 8 + wid) * NPG;
        if (node0 >= N_NODES) return;
        const float* hbuf = g_h[tg & 1];
        float*       zbuf = g_z[tg & 1];

        // stage 4 h rows (256 floats) via 2 coalesced LDG.128 per lane
        const float4* hsrc = reinterpret_cast<const float4*>(hbuf + (size_t)node0 * HD);
        float4* hdst = reinterpret_cast<float4*>(sHG[wid]);
        hdst[lane]      = hsrc[lane];
        hdst[lane + 32] = hsrc[lane + 32];
        __syncwarp();

        float z[NPG] = {0.f, 0.f, 0.f, 0.f};
        const float* wc = sWT + lane * WPITCH;
#pragma unroll
        for (int q = 0; q < 16; q++) {
            float4 wv = *reinterpret_cast<const float4*>(wc + 4 * q);   // conflict-free
#pragma unroll
            for (int n = 0; n < NPG; n++) {
                float4 hv = *reinterpret_cast<const float4*>(sHG[wid] + n * HD + 4 * q);
                z[n] = fmaf(hv.x, wv.x, z[n]);
                z[n] = fmaf(hv.y, wv.y, z[n]);
                z[n] = fmaf(hv.z, wv.z, z[n]);
                z[n] = fmaf(hv.w, wv.w, z[n]);
            }
        }
#pragma unroll
        for (int n = 0; n < NPG; n++)
            zbuf[(node0 + n) * ZD + lane] = z[n];
    } else if (bx < NB_L1 + NB_GEM + NB_L2) {
        int tl = t - 2;
        if (tl < 0) return;
        int node = (bx - NB_L1 - NB_GEM) * 8 + wid;
        if (node >= N_NODES) return;
        layer2_work(b2, g_z[tl & 1], out_l2, tl, node, lane);
    } else if (bx < NB_L1 + NB_GEM + NB_L2 + NB_BIN) {
        int tb = t + 2;
        if (tb >= T_STEPS) return;
        int e = (bx - NB_L1 - NB_GEM - NB_L2) * 256 + threadIdx.x;
        if (e < E_EDGES) bin_work(tb, e, ei, ew);
    } else {
        int td = t + 1;
        if (td >= T_STEPS) return;
        int i = (bx - NB_L1 - NB_GEM - NB_L2 - NB_BIN) * 256 + threadIdx.x;
        if (i < N_NODES) dinv_work(td * N_NODES + i);
    }
}

// prologue helpers
__global__ void k_bin01(const int* __restrict__ ei, const float* __restrict__ ew) {
    int idx = blockIdx.x * blockDim.x + threadIdx.x;   // 2*E threads
    if (idx >= 2 * E_EDGES) return;
    int t = idx < E_EDGES ? 0 : 1;
    int e = idx - t * E_EDGES;
    bin_work(t, e, ei, ew);
}

__global__ void k_dinv0() {
    int i = blockIdx.x * blockDim.x + threadIdx.x;
    if (i < N_NODES) dinv_work(i);
}

// ============================================================
// Launch
// ============================================================
extern "C" void kernel_launch(void* const* d_in, const int* in_sizes, int n_in,
                              void* d_out, int out_size) {
    const float* x  = (const float*)d_in[0];   // [N, 128]
    const int*   ei = (const int*)d_in[1];     // [T, 2, E]
    const float* ew = (const float*)d_in[2];   // [T, E]
    const float* W1 = (const float*)d_in[3];   // [128, 64]
    const float* b1 = (const float*)d_in[4];   // [64]
    const float* W2 = (const float*)d_in[5];   // [64, 32]
    const float* b2 = (const float*)d_in[6];   // [32]
    float* out = (float*)d_out;                // [T, N, 32]

    const int B = 256;

    // prologue
    k_init<<<(T_STEPS * N_NODES + B - 1) / B, B>>>();
    k_xw1<<<NB_L1, B>>>(x, W1);
    k_bin01<<<(2 * E_EDGES + B - 1) / B, B>>>(ei, ew);
    k_dinv0<<<(N_NODES + B - 1) / B, B>>>();

    // 3-stage pipelined steps: gather1(t) | gemm(t-1) | layer2(t-2) | bin(t+2) | dinv(t+1)
    const int GRID = NB_L1 + NB_GEM + NB_L2 + NB_BIN + NB_DNV;
    for (int t = 0; t < T_STEPS + 2; t++) {
        float* out_l2 = out + (size_t)(t - 2) * N_NODES * ZD;  // valid when t >= 2
        k_step<<<GRID, B>>>(b1, W2, b2, out_l2, t, ei, ew);
    }
}

// round 13
// speedup vs baseline: 1.1920x; 1.1920x over previous
#include <cuda_runtime.h>
#include <cuda_fp16.h>

#define N_NODES 50000
#define T_STEPS 8
#define E_EDGES 800000
#define XD 128
#define HD 64
#define ZD 32
#define CAP 96       // Poisson(16) tail beyond 96 ~ e^-80

#define NB_L   6250  // layer role blocks: 50000 nodes / 8 warps per block
#define NB_BIN 3125  // bin role blocks: 800000 edges / 256
#define NB_DNV 196   // dinv role blocks: 50000 / 256

// ---- scratch (no allocations allowed) ----
__device__ __half g_xW1[N_NODES * HD];                      // x @ W1, fp16 (6.4 MB)
__device__ __half g_hW2[2][N_NODES * ZD];                   // z = h@W2, fp16, dbl-buffered
__device__ unsigned long long g_pack[T_STEPS * N_NODES];    // (count<<52)|fixed32(sum w)
__device__ float  g_dinv[T_STEPS * N_NODES];
__device__ int    g_count[T_STEPS * N_NODES];
__device__ int2   g_bins[(size_t)T_STEPS * N_NODES * CAP];  // (src, bits(w|nrm)) (307 MB)

// ============================================================
// Setup: g_xW1 = x @ W1   (warp per node, W1 in shared) -> fp16
// ============================================================
__global__ void k_xw1(const float* __restrict__ x, const float* __restrict__ W1) {
    __shared__ float sW[XD * HD];
    for (int i = threadIdx.x; i < XD * HD; i += blockDim.x) sW[i] = W1[i];
    __syncthreads();

    int node = blockIdx.x * (blockDim.x >> 5) + (threadIdx.x >> 5);
    int lane = threadIdx.x & 31;
    if (node >= N_NODES) return;

    const float* xr = x + node * XD;
    float xv[4];
    xv[0] = xr[lane];
    xv[1] = xr[lane + 32];
    xv[2] = xr[lane + 64];
    xv[3] = xr[lane + 96];

    float a0 = 0.f, a1 = 0.f;
#pragma unroll
    for (int q = 0; q < 4; q++) {
#pragma unroll
        for (int k = 0; k < 32; k++) {
            float xk = __shfl_sync(0xffffffffu, xv[q], k);
            int kk = q * 32 + k;
            a0 = fmaf(xk, sW[kk * HD + lane], a0);
            a1 = fmaf(xk, sW[kk * HD + lane + 32], a1);
        }
    }
    g_xW1[node * HD + lane]      = __float2half(a0);
    g_xW1[node * HD + lane + 32] = __float2half(a1);
}

// ============================================================
// Work bodies
// ============================================================
__global__ void k_init() {
    int i = blockIdx.x * blockDim.x + threadIdx.x;
    if (i < T_STEPS * N_NODES) g_pack[i] = 0ull;
}

__device__ __forceinline__ void bin_work(int t, int e, const int* __restrict__ ei,
                                         const float* __restrict__ ew) {
    const int* src = ei + (size_t)t * 2 * E_EDGES;
    const int* dst = src + E_EDGES;
    int s = src[e];
    int d = dst[e];
    float w = ew[(size_t)t * E_EDGES + e];
    int base = t * N_NODES + d;
    unsigned long long add =
        (1ull << 52) | (unsigned long long)(w * 4294967296.0f);
    unsigned long long old = atomicAdd(&g_pack[base], add);
    int p = (int)(old >> 52);
    if (p < CAP) g_bins[(size_t)base * CAP + p] = make_int2(s, __float_as_int(w));
}

__device__ __forceinline__ void dinv_work(int i) {
    unsigned long long v = g_pack[i];
    g_count[i] = (int)(v >> 52);
    float deg = 1.0f + (float)(v & ((1ull << 52) - 1ull)) * (1.0f / 4294967296.0f);
    g_dinv[i] = rsqrtf(deg);
}

// layer1: gather(xW1 fp16) + b1 + relu + (h @ W2) -> z (fp16)  (R10 structure)
__device__ __forceinline__ void layer1_work(const float* __restrict__ b1,
                                            const float* sW, int t,
                                            __half* __restrict__ zbuf,
                                            int node, int lane) {
    int base = t * N_NODES + node;
    float dv = g_dinv[base];
    int   c  = min(g_count[base], CAP);
    const float* dinv_t = g_dinv + t * N_NODES;
    int2* bp = g_bins + (size_t)base * CAP;

    // coalesced prefetch into registers: lane handles entries lane, +32, +64
    int   sj[3];
    float nj[3];
#pragma unroll
    for (int r = 0; r < 3; r++) {
        int j = lane + 32 * r;
        sj[r] = 0; nj[r] = 0.f;
        if (j < c) {
            int2 ent = bp[j];
            int s = ent.x;
            float nrm = dinv_t[s] * __int_as_float(ent.y) * dv;
            sj[r] = s;
            nj[r] = nrm;
            bp[j].y = __float_as_int(nrm);  // layer 2 reuses nrm
        }
    }

    const __half2* xw = reinterpret_cast<const __half2*>(g_xW1);

    float2 me = __half22float2(xw[node * 32 + lane]);   // self-loop, norm = dv*dv
    float accx = me.x * (dv * dv);
    float accy = me.y * (dv * dv);

#pragma unroll
    for (int r = 0; r < 3; r++) {
        int cnt = min(max(c - 32 * r, 0), 32);
#pragma unroll 8
        for (int k = 0; k < cnt; k++) {
            int   s   = __shfl_sync(0xffffffffu, sj[r], k);
            float nrm = __shfl_sync(0xffffffffu, nj[r], k);
            float2 v = __half22float2(xw[s * 32 + lane]);  // 128B coalesced row
            accx = fmaf(v.x, nrm, accx);
            accy = fmaf(v.y, nrm, accy);
        }
    }

    float2 bb = reinterpret_cast<const float2*>(b1)[lane];
    float h0 = fmaxf(accx + bb.x, 0.0f);
    float h1 = fmaxf(accy + bb.y, 0.0f);

    float z = 0.f;
#pragma unroll
    for (int k = 0; k < 32; k++) {
        float hk0 = __shfl_sync(0xffffffffu, h0, k);
        float hk1 = __shfl_sync(0xffffffffu, h1, k);
        z = fmaf(hk0, sW[(2 * k) * ZD + lane], z);
        z = fmaf(hk1, sW[(2 * k + 1) * ZD + lane], z);
    }
    zbuf[node * ZD + lane] = __float2half(z);
}

// layer2: gather(z fp16) + b2 + tanh -> out_t  (R10 structure; bins hold nrm)
__device__ __forceinline__ void layer2_work(const float* __restrict__ b2,
                                            const __half* __restrict__ zbuf,
                                            float* __restrict__ out_t, int t,
                                            int node, int lane) {
    int base = t * N_NODES + node;
    float dv = g_dinv[base];
    int   c  = min(g_count[base], CAP);
    const int2* bp = g_bins + (size_t)base * CAP;

    int   sj[3];
    float nj[3];
#pragma unroll
    for (int r = 0; r < 3; r++) {
        int j = lane + 32 * r;
        sj[r] = 0; nj[r] = 0.f;
        if (j < c) {
            int2 ent = bp[j];
            sj[r] = ent.x;
            nj[r] = __int_as_float(ent.y);  // nrm
        }
    }

    float acc = __half2float(zbuf[node * ZD + lane]) * (dv * dv);

#pragma unroll
    for (int r = 0; r < 3; r++) {
        int cnt = min(max(c - 32 * r, 0), 32);
#pragma unroll 8
        for (int k = 0; k < cnt; k++) {
            int   s   = __shfl_sync(0xffffffffu, sj[r], k);
            float nrm = __shfl_sync(0xffffffffu, nj[r], k);
            acc = fmaf(__half2float(zbuf[s * ZD + lane]), nrm, acc);  // 64B rows
        }
    }
    out_t[node * ZD + lane] = tanhf(acc + b2[lane]);
}

// ============================================================
// Pipelined step kernel (R10 role order):
//   [0, NB_L)                layer1(t)    -> z_w
//   [NB_L, 2*NB_L)           layer2(t-1)  (if t >= 1)
//   [2*NB_L, +NB_BIN)        bin(t+2)     (if t+2 < T)
//   [2*NB_L+NB_BIN, +NB_DNV) dinv(t+1)    (if t+1 < T)
// ============================================================
__global__ void k_step(const float* __restrict__ b1, const float* __restrict__ W2,
                       const float* __restrict__ b2,
                       float* __restrict__ out_prev, int t,
                       const __half* __restrict__ z_r, __half* __restrict__ z_w,
                       const int* __restrict__ ei, const float* __restrict__ ew) {
    int bx = blockIdx.x;
    int lane = threadIdx.x & 31;

    if (bx < NB_L) {
        __shared__ float sW[HD * ZD];
        for (int i = threadIdx.x; i < HD * ZD; i += blockDim.x) sW[i] = W2[i];
        __syncthreads();
        int node = bx * 8 + (threadIdx.x >> 5);
        if (node >= N_NODES) return;
        layer1_work(b1, sW, t, z_w, node, lane);
    } else if (bx < 2 * NB_L) {
        if (t == 0) return;
        int node = (bx - NB_L) * 8 + (threadIdx.x >> 5);
        if (node >= N_NODES) return;
        layer2_work(b2, z_r, out_prev, t - 1, node, lane);
    } else if (bx < 2 * NB_L + NB_BIN) {
        int tb = t + 2;
        if (tb >= T_STEPS) return;
        int e = (bx - 2 * NB_L) * 256 + threadIdx.x;
        if (e < E_EDGES) bin_work(tb, e, ei, ew);
    } else {
        int td = t + 1;
        if (td >= T_STEPS) return;
        int i = (bx - 2 * NB_L - NB_BIN) * 256 + threadIdx.x;
        if (i < N_NODES) dinv_work(td * N_NODES + i);
    }
}

// prologue helpers (R10)
__global__ void k_bin01(const int* __restrict__ ei, const float* __restrict__ ew) {
    int idx = blockIdx.x * blockDim.x + threadIdx.x;   // 2*E threads
    if (idx >= 2 * E_EDGES) return;
    int t = idx < E_EDGES ? 0 : 1;
    int e = idx - t * E_EDGES;
    bin_work(t, e, ei, ew);
}

__global__ void k_dinv0() {
    int i = blockIdx.x * blockDim.x + threadIdx.x;
    if (i < N_NODES) dinv_work(i);
}

__global__ void k_layer2_last(const float* __restrict__ b2, float* __restrict__ out_t,
                              const __half* __restrict__ zbuf) {
    int node = blockIdx.x * (blockDim.x >> 5) + (threadIdx.x >> 5);
    int lane = threadIdx.x & 31;
    if (node >= N_NODES) return;
    layer2_work(b2, zbuf, out_t, T_STEPS - 1, node, lane);
}

// ============================================================
// Launch
// ============================================================
extern "C" void kernel_launch(void* const* d_in, const int* in_sizes, int n_in,
                              void* d_out, int out_size) {
    const float* x  = (const float*)d_in[0];   // [N, 128]
    const int*   ei = (const int*)d_in[1];     // [T, 2, E]
    const float* ew = (const float*)d_in[2];   // [T, E]
    const float* W1 = (const float*)d_in[3];   // [128, 64]
    const float* b1 = (const float*)d_in[4];   // [64]
    const float* W2 = (const float*)d_in[5];   // [64, 32]
    const float* b2 = (const float*)d_in[6];   // [32]
    float* out = (float*)d_out;                // [T, N, 32]

    const int B = 256;

    __half* z0; __half* z1;
    cudaGetSymbolAddress((void**)&z0, g_hW2);
    z1 = z0 + (size_t)N_NODES * ZD;

    // prologue
    k_init<<<(T_STEPS * N_NODES + B - 1) / B, B>>>();
    k_xw1<<<NB_L, B>>>(x, W1);
    k_bin01<<<(2 * E_EDGES + B - 1) / B, B>>>(ei, ew);
    k_dinv0<<<(N_NODES + B - 1) / B, B>>>();

    // pipelined steps
    const int GRID = 2 * NB_L + NB_BIN + NB_DNV;
    for (int t = 0; t < T_STEPS; t++) {
        float* out_prev = out + (size_t)(t - 1) * N_NODES * ZD;  // unused at t=0
        __half* z_r = (t & 1) ? z0 : z1;
        __half* z_w = (t & 1) ? z1 : z0;
        k_step<<<GRID, B>>>(b1, W2, b2, out_prev, t, z_r, z_w, ei, ew);
    }

    // epilogue: layer2 for t = 7
    k_layer2_last<<<NB_L, B>>>(b2, out + (size_t)(T_STEPS - 1) * N_NODES * ZD,
                               ((T_STEPS - 1) & 1) ? z1 : z0);
}

// round 14
// speedup vs baseline: 1.2085x; 1.0138x over previous
#include <cuda_runtime.h>
#include <cuda_fp16.h>

#define N_NODES 50000
#define T_STEPS 8
#define E_EDGES 800000
#define XD 128
#define HD 64
#define ZD 32
#define CAP 96       // Poisson(16) tail beyond 96 ~ e^-80

#define NB_L   6250  // layer role blocks: 50000 nodes / 8 warps per block
#define NB_BIN 3125  // bin role blocks: 800000 edges / 256
#define NB_DNV 196   // dinv role blocks: 50000 / 256
#define NB_INI 1563  // init role blocks: 400000 / 256

// ---- scratch (no allocations allowed) ----
__device__ __half g_xW1[N_NODES * HD];                      // x @ W1, fp16 (6.4 MB)
__device__ __half g_hW2[2][N_NODES * ZD];                   // z = h@W2, fp16, dbl-buffered
__device__ unsigned long long g_pack[T_STEPS * N_NODES];    // (count<<52)|fixed32(sum w)
__device__ float  g_dinv[T_STEPS * N_NODES];
__device__ int    g_count[T_STEPS * N_NODES];
__device__ int2   g_bins[(size_t)T_STEPS * N_NODES * CAP];  // (src, bits(w)|packed) (307 MB)

// pack helpers: low 16 bits = src node (< 65536), high 16 bits = fp16(nrm)
__device__ __forceinline__ unsigned pack_sn(int s, float nrm) {
    return (unsigned)s | ((unsigned)__half_as_ushort(__float2half(nrm)) << 16);
}
__device__ __forceinline__ int   up_s(unsigned p)   { return (int)(p & 0xFFFFu); }
__device__ __forceinline__ float up_n(unsigned p)   {
    return __half2float(__ushort_as_half((unsigned short)(p >> 16)));
}

// ============================================================
// Work bodies
// ============================================================
__device__ __forceinline__ void xw1_work(const float* __restrict__ x,
                                         const float* sW, int node, int lane) {
    const float* xr = x + node * XD;
    float xv[4];
    xv[0] = xr[lane];
    xv[1] = xr[lane + 32];
    xv[2] = xr[lane + 64];
    xv[3] = xr[lane + 96];

    float a0 = 0.f, a1 = 0.f;
#pragma unroll
    for (int q = 0; q < 4; q++) {
#pragma unroll
        for (int k = 0; k < 32; k++) {
            float xk = __shfl_sync(0xffffffffu, xv[q], k);
            int kk = q * 32 + k;
            a0 = fmaf(xk, sW[kk * HD + lane], a0);
            a1 = fmaf(xk, sW[kk * HD + lane + 32], a1);
        }
    }
    g_xW1[node * HD + lane]      = __float2half(a0);
    g_xW1[node * HD + lane + 32] = __float2half(a1);
}

__device__ __forceinline__ void bin_work(int t, int e, const int* __restrict__ ei,
                                         const float* __restrict__ ew) {
    const int* src = ei + (size_t)t * 2 * E_EDGES;
    const int* dst = src + E_EDGES;
    int s = src[e];
    int d = dst[e];
    float w = ew[(size_t)t * E_EDGES + e];
    int base = t * N_NODES + d;
    unsigned long long add =
        (1ull << 52) | (unsigned long long)(w * 4294967296.0f);
    unsigned long long old = atomicAdd(&g_pack[base], add);
    int p = (int)(old >> 52);
    if (p < CAP) g_bins[(size_t)base * CAP + p] = make_int2(s, __float_as_int(w));
}

__device__ __forceinline__ void dinv_work(int i) {
    unsigned long long v = g_pack[i];
    g_count[i] = (int)(v >> 52);
    float deg = 1.0f + (float)(v & ((1ull << 52) - 1ull)) * (1.0f / 4294967296.0f);
    g_dinv[i] = rsqrtf(deg);
}

// layer1: gather(xW1 fp16) + b1 + relu + (h @ W2) -> z (fp16)
// Prefetch packs (s, fp16 nrm) into ONE word; inner loop = 1 SHFL/neighbor.
__device__ __forceinline__ void layer1_work(const float* __restrict__ b1,
                                            const float* sW, int t,
                                            __half* __restrict__ zbuf,
                                            int node, int lane) {
    int base = t * N_NODES + node;
    float dv = g_dinv[base];
    int   c  = min(g_count[base], CAP);
    const float* dinv_t = g_dinv + t * N_NODES;
    int2* bp = g_bins + (size_t)base * CAP;

    // coalesced prefetch: lane handles entries lane, +32, +64; pack (s, nrm)
    unsigned pj[3];
#pragma unroll
    for (int r = 0; r < 3; r++) {
        int j = lane + 32 * r;
        pj[r] = 0u;
        if (j < c) {
            int2 ent = bp[j];
            int s = ent.x;
            float nrm = dinv_t[s] * __int_as_float(ent.y) * dv;
            unsigned p = pack_sn(s, nrm);
            pj[r] = p;
            bp[j].y = (int)p;               // layer 2 reuses packed (s, nrm)
        }
    }

    const __half2* xw = reinterpret_cast<const __half2*>(g_xW1);

    float2 me = __half22float2(xw[node * 32 + lane]);   // self-loop, norm = dv*dv
    float accx = me.x * (dv * dv);
    float accy = me.y * (dv * dv);

#pragma unroll
    for (int r = 0; r < 3; r++) {
        int cnt = min(max(c - 32 * r, 0), 32);
#pragma unroll 8
        for (int k = 0; k < cnt; k++) {
            unsigned p = __shfl_sync(0xffffffffu, pj[r], k);   // ONE shfl
            int   s   = up_s(p);
            float nrm = up_n(p);
            float2 v = __half22float2(xw[s * 32 + lane]);      // 128B coalesced row
            accx = fmaf(v.x, nrm, accx);
            accy = fmaf(v.y, nrm, accy);
        }
    }

    float2 bb = reinterpret_cast<const float2*>(b1)[lane];
    float h0 = fmaxf(accx + bb.x, 0.0f);
    float h1 = fmaxf(accy + bb.y, 0.0f);

    float z = 0.f;
#pragma unroll
    for (int k = 0; k < 32; k++) {
        float hk0 = __shfl_sync(0xffffffffu, h0, k);
        float hk1 = __shfl_sync(0xffffffffu, h1, k);
        z = fmaf(hk0, sW[(2 * k) * ZD + lane], z);
        z = fmaf(hk1, sW[(2 * k + 1) * ZD + lane], z);
    }
    zbuf[node * ZD + lane] = __float2half(z);
}

// layer2: gather(z fp16) + b2 + tanh -> out_t  (bins hold packed (s, nrm))
__device__ __forceinline__ void layer2_work(const float* __restrict__ b2,
                                            const __half* __restrict__ zbuf,
                                            float* __restrict__ out_t, int t,
                                            int node, int lane) {
    int base = t * N_NODES + node;
    float dv = g_dinv[base];
    int   c  = min(g_count[base], CAP);
    const int2* bp = g_bins + (size_t)base * CAP;

    unsigned pj[3];
#pragma unroll
    for (int r = 0; r < 3; r++) {
        int j = lane + 32 * r;
        pj[r] = 0u;
        if (j < c) pj[r] = (unsigned)bp[j].y;   // packed (s, nrm)
    }

    float acc = __half2float(zbuf[node * ZD + lane]) * (dv * dv);

#pragma unroll
    for (int r = 0; r < 3; r++) {
        int cnt = min(max(c - 32 * r, 0), 32);
#pragma unroll 8
        for (int k = 0; k < cnt; k++) {
            unsigned p = __shfl_sync(0xffffffffu, pj[r], k);   // ONE shfl
            int   s   = up_s(p);
            float nrm = up_n(p);
            acc = fmaf(__half2float(zbuf[s * ZD + lane]), nrm, acc);  // 64B rows
        }
    }
    out_t[node * ZD + lane] = tanhf(acc + b2[lane]);
}

// ============================================================
// Fused prologue A: init role + xw1 role
//   [0, NB_INI)          g_pack init
//   [NB_INI, +NB_L)      xw1
// ============================================================
__global__ void k_prologA(const float* __restrict__ x, const float* __restrict__ W1) {
    int bx = blockIdx.x;
    if (bx < NB_INI) {
        int i = bx * 256 + threadIdx.x;
        if (i < T_STEPS * N_NODES) g_pack[i] = 0ull;
    } else {
        __shared__ float sW[XD * HD];
        for (int i = threadIdx.x; i < XD * HD; i += blockDim.x) sW[i] = W1[i];
        __syncthreads();
        int node = (bx - NB_INI) * 8 + (threadIdx.x >> 5);
        int lane = threadIdx.x & 31;
        if (node >= N_NODES) return;
        xw1_work(x, sW, node, lane);
    }
}

__global__ void k_bin01(const int* __restrict__ ei, const float* __restrict__ ew) {
    int idx = blockIdx.x * blockDim.x + threadIdx.x;   // 2*E threads
    if (idx >= 2 * E_EDGES) return;
    int t = idx < E_EDGES ? 0 : 1;
    int e = idx - t * E_EDGES;
    bin_work(t, e, ei, ew);
}

__global__ void k_dinv0() {
    int i = blockIdx.x * blockDim.x + threadIdx.x;
    if (i < N_NODES) dinv_work(i);
}

// ============================================================
// Pipelined step kernel (R10/R13 role order):
//   [0, NB_L)                layer1(t)    -> z_w
//   [NB_L, 2*NB_L)           layer2(t-1)  (if t >= 1)
//   [2*NB_L, +NB_BIN)        bin(t+2)     (if t+2 < T)
//   [2*NB_L+NB_BIN, +NB_DNV) dinv(t+1)    (if t+1 < T)
// ============================================================
__global__ void k_step(const float* __restrict__ b1, const float* __restrict__ W2,
                       const float* __restrict__ b2,
                       float* __restrict__ out_prev, int t,
                       const __half* __restrict__ z_r, __half* __restrict__ z_w,
                       const int* __restrict__ ei, const float* __restrict__ ew) {
    int bx = blockIdx.x;
    int lane = threadIdx.x & 31;

    if (bx < NB_L) {
        __shared__ float sW[HD * ZD];
        for (int i = threadIdx.x; i < HD * ZD; i += blockDim.x) sW[i] = W2[i];
        __syncthreads();
        int node = bx * 8 + (threadIdx.x >> 5);
        if (node >= N_NODES) return;
        layer1_work(b1, sW, t, z_w, node, lane);
    } else if (bx < 2 * NB_L) {
        if (t == 0) return;
        int node = (bx - NB_L) * 8 + (threadIdx.x >> 5);
        if (node >= N_NODES) return;
        layer2_work(b2, z_r, out_prev, t - 1, node, lane);
    } else if (bx < 2 * NB_L + NB_BIN) {
        int tb = t + 2;
        if (tb >= T_STEPS) return;
        int e = (bx - 2 * NB_L) * 256 + threadIdx.x;
        if (e < E_EDGES) bin_work(tb, e, ei, ew);
    } else {
        int td = t + 1;
        if (td >= T_STEPS) return;
        int i = (bx - 2 * NB_L - NB_BIN) * 256 + threadIdx.x;
        if (i < N_NODES) dinv_work(td * N_NODES + i);
    }
}

__global__ void k_layer2_last(const float* __restrict__ b2, float* __restrict__ out_t,
                              const __half* __restrict__ zbuf) {
    int node = blockIdx.x * (blockDim.x >> 5) + (threadIdx.x >> 5);
    int lane = threadIdx.x & 31;
    if (node >= N_NODES) return;
    layer2_work(b2, zbuf, out_t, T_STEPS - 1, node, lane);
}

// ============================================================
// Launch
// ============================================================
extern "C" void kernel_launch(void* const* d_in, const int* in_sizes, int n_in,
                              void* d_out, int out_size) {
    const float* x  = (const float*)d_in[0];   // [N, 128]
    const int*   ei = (const int*)d_in[1];     // [T, 2, E]
    const float* ew = (const float*)d_in[2];   // [T, E]
    const float* W1 = (const float*)d_in[3];   // [128, 64]
    const float* b1 = (const float*)d_in[4];   // [64]
    const float* W2 = (const float*)d_in[5];   // [64, 32]
    const float* b2 = (const float*)d_in[6];   // [32]
    float* out = (float*)d_out;                // [T, N, 32]

    const int B = 256;

    __half* z0; __half* z1;
    cudaGetSymbolAddress((void**)&z0, g_hW2);
    z1 = z0 + (size_t)N_NODES * ZD;

    // prologue
    k_prologA<<<NB_INI + NB_L, B>>>(x, W1);
    k_bin01<<<(2 * E_EDGES + B - 1) / B, B>>>(ei, ew);
    k_dinv0<<<(N_NODES + B - 1) / B, B>>>();

    // pipelined steps
    const int GRID = 2 * NB_L + NB_BIN + NB_DNV;
    for (int t = 0; t < T_STEPS; t++) {
        float* out_prev = out + (size_t)(t - 1) * N_NODES * ZD;  // unused at t=0
        __half* z_r = (t & 1) ? z0 : z1;
        __half* z_w = (t & 1) ? z1 : z0;
        k_step<<<GRID, B>>>(b1, W2, b2, out_prev, t, z_r, z_w, ei, ew);
    }

    // epilogue: layer2 for t = 7
    k_layer2_last<<<NB_L, B>>>(b2, out + (size_t)(T_STEPS - 1) * N_NODES * ZD,
                               ((T_STEPS - 1) & 1) ? z1 : z0);
}

// round 16
// speedup vs baseline: 1.2902x; 1.0677x over previous
#include <cuda_runtime.h>
#include <cuda_fp16.h>

#define N_NODES 50000
#define T_STEPS 8
#define E_EDGES 800000
#define XD 128
#define HD 64
#define ZD 32
#define CAP 96       // Poisson(16) tail beyond 96 ~ e^-80

#define NB_L   6250  // layer role blocks: 50000 nodes / 8 warps per block
#define NB_BIN 3125  // bin role blocks: 800000 edges / 256
#define NB_DNV 196   // dinv role blocks: 50000 / 256
#define NB_INI 1563  // init role blocks: 400000 / 256

// ---- scratch (no allocations allowed) ----
__device__ __half g_xW1[N_NODES * HD];                      // x @ W1, fp16 (6.4 MB)
__device__ __half g_hW2[2][N_NODES * ZD];                   // z = h@W2, fp16, dbl-buffered
__device__ unsigned long long g_pack[T_STEPS * N_NODES];    // (count<<52)|fixed32(sum w)
__device__ float  g_dinv[T_STEPS * N_NODES];
__device__ int    g_count[T_STEPS * N_NODES];
__device__ int2   g_bins[(size_t)T_STEPS * N_NODES * CAP];  // (src, bits(w)|packed) (307 MB)

// pack helpers: low 16 bits = src node (< 65536), high 16 bits = fp16(nrm)
__device__ __forceinline__ unsigned pack_sn(int s, float nrm) {
    return (unsigned)s | ((unsigned)__half_as_ushort(__float2half(nrm)) << 16);
}
__device__ __forceinline__ int   up_s(unsigned p)   { return (int)(p & 0xFFFFu); }
__device__ __forceinline__ float up_n(unsigned p)   {
    return __half2float(__ushort_as_half((unsigned short)(p >> 16)));
}

// bit casts (no intrinsic for half2<->uint in this toolkit)
__device__ __forceinline__ unsigned h2_as_u(__half2 v) {
    unsigned u; *reinterpret_cast<__half2*>(&u) = v; return u;
}
__device__ __forceinline__ __half2 u_as_h2(unsigned u) {
    return *reinterpret_cast<__half2*>(&u);
}

// ============================================================
// Work bodies
// ============================================================
__device__ __forceinline__ void xw1_work(const float* __restrict__ x,
                                         const float* sW, int node, int lane) {
    const float* xr = x + node * XD;
    float xv[4];
    xv[0] = xr[lane];
    xv[1] = xr[lane + 32];
    xv[2] = xr[lane + 64];
    xv[3] = xr[lane + 96];

    float a0 = 0.f, a1 = 0.f;
#pragma unroll
    for (int q = 0; q < 4; q++) {
#pragma unroll
        for (int k = 0; k < 32; k++) {
            float xk = __shfl_sync(0xffffffffu, xv[q], k);
            int kk = q * 32 + k;
            a0 = fmaf(xk, sW[kk * HD + lane], a0);
            a1 = fmaf(xk, sW[kk * HD + lane + 32], a1);
        }
    }
    g_xW1[node * HD + lane]      = __float2half(a0);
    g_xW1[node * HD + lane + 32] = __float2half(a1);
}

__device__ __forceinline__ void bin_work(int t, int e, const int* __restrict__ ei,
                                         const float* __restrict__ ew) {
    const int* src = ei + (size_t)t * 2 * E_EDGES;
    const int* dst = src + E_EDGES;
    int s = src[e];
    int d = dst[e];
    float w = ew[(size_t)t * E_EDGES + e];
    int base = t * N_NODES + d;
    unsigned long long add =
        (1ull << 52) | (unsigned long long)(w * 4294967296.0f);
    unsigned long long old = atomicAdd(&g_pack[base], add);
    int p = (int)(old >> 52);
    if (p < CAP) g_bins[(size_t)base * CAP + p] = make_int2(s, __float_as_int(w));
}

__device__ __forceinline__ void dinv_work(int i) {
    unsigned long long v = g_pack[i];
    g_count[i] = (int)(v >> 52);
    float deg = 1.0f + (float)(v & ((1ull << 52) - 1ull)) * (1.0f / 4294967296.0f);
    g_dinv[i] = rsqrtf(deg);
}

// layer1: gather(xW1 fp16) + b1 + relu + (h @ W2) -> z (fp16)
// Gather: 1 SHFL/neighbor (packed).  Tail: packed half2 h -> 32 SHFL + 32 LDS.64.
// sW2p[k*32 + lane] = (W2[2k][lane], W2[2k+1][lane])
__device__ __forceinline__ void layer1_work(const float* __restrict__ b1,
                                            const float2* sW2p, int t,
                                            __half* __restrict__ zbuf,
                                            int node, int lane) {
    int base = t * N_NODES + node;
    float dv = g_dinv[base];
    int   c  = min(g_count[base], CAP);
    const float* dinv_t = g_dinv + t * N_NODES;
    int2* bp = g_bins + (size_t)base * CAP;

    // coalesced prefetch: lane handles entries lane, +32, +64; pack (s, nrm)
    unsigned pj[3];
#pragma unroll
    for (int r = 0; r < 3; r++) {
        int j = lane + 32 * r;
        pj[r] = 0u;
        if (j < c) {
            int2 ent = bp[j];
            int s = ent.x;
            float nrm = dinv_t[s] * __int_as_float(ent.y) * dv;
            unsigned p = pack_sn(s, nrm);
            pj[r] = p;
            bp[j].y = (int)p;               // layer 2 reuses packed (s, nrm)
        }
    }

    const __half2* xw = reinterpret_cast<const __half2*>(g_xW1);

    float2 me = __half22float2(xw[node * 32 + lane]);   // self-loop, norm = dv*dv
    float accx = me.x * (dv * dv);
    float accy = me.y * (dv * dv);

#pragma unroll
    for (int r = 0; r < 3; r++) {
        int cnt = min(max(c - 32 * r, 0), 32);
#pragma unroll 8
        for (int k = 0; k < cnt; k++) {
            unsigned p = __shfl_sync(0xffffffffu, pj[r], k);   // ONE shfl
            int   s   = up_s(p);
            float nrm = up_n(p);
            float2 v = __half22float2(xw[s * 32 + lane]);      // 128B coalesced row
            accx = fmaf(v.x, nrm, accx);
            accy = fmaf(v.y, nrm, accy);
        }
    }

    float2 bb = reinterpret_cast<const float2*>(b1)[lane];
    float h0 = fmaxf(accx + bb.x, 0.0f);   // h[2*lane]
    float h1 = fmaxf(accy + bb.y, 0.0f);   // h[2*lane+1]

    // pack h pair -> half2; tail = 32 SHFL + 32 LDS.64 + 64 FMA (fp32 accum)
    unsigned hp = h2_as_u(__floats2half2_rn(h0, h1));
    float z0 = 0.f, z1 = 0.f;
#pragma unroll
    for (int k = 0; k < 32; k += 2) {
        unsigned pa = __shfl_sync(0xffffffffu, hp, k);
        float2 ha = __half22float2(u_as_h2(pa));
        float2 wa = sW2p[k * 32 + lane];
        z0 = fmaf(ha.x, wa.x, z0);
        z0 = fmaf(ha.y, wa.y, z0);
        unsigned pb = __shfl_sync(0xffffffffu, hp, k + 1);
        float2 hb = __half22float2(u_as_h2(pb));
        float2 wb = sW2p[(k + 1) * 32 + lane];
        z1 = fmaf(hb.x, wb.x, z1);
        z1 = fmaf(hb.y, wb.y, z1);
    }
    zbuf[node * ZD + lane] = __float2half(z0 + z1);
}

// layer2: gather(z fp16) + b2 + tanh -> out_t  (bins hold packed (s, nrm))
__device__ __forceinline__ void layer2_work(const float* __restrict__ b2,
                                            const __half* __restrict__ zbuf,
                                            float* __restrict__ out_t, int t,
                                            int node, int lane) {
    int base = t * N_NODES + node;
    float dv = g_dinv[base];
    int   c  = min(g_count[base], CAP);
    const int2* bp = g_bins + (size_t)base * CAP;

    unsigned pj[3];
#pragma unroll
    for (int r = 0; r < 3; r++) {
        int j = lane + 32 * r;
        pj[r] = 0u;
        if (j < c) pj[r] = (unsigned)bp[j].y;   // packed (s, nrm)
    }

    float acc = __half2float(zbuf[node * ZD + lane]) * (dv * dv);

#pragma unroll
    for (int r = 0; r < 3; r++) {
        int cnt = min(max(c - 32 * r, 0), 32);
#pragma unroll 8
        for (int k = 0; k < cnt; k++) {
            unsigned p = __shfl_sync(0xffffffffu, pj[r], k);   // ONE shfl
            int   s   = up_s(p);
            float nrm = up_n(p);
            acc = fmaf(__half2float(zbuf[s * ZD + lane]), nrm, acc);  // 64B rows
        }
    }
    out_t[node * ZD + lane] = tanhf(acc + b2[lane]);
}

// ============================================================
// Fused prologue A: init role + xw1 role
// ============================================================
__global__ void k_prologA(const float* __restrict__ x, const float* __restrict__ W1) {
    int bx = blockIdx.x;
    if (bx < NB_INI) {
        int i = bx * 256 + threadIdx.x;
        if (i < T_STEPS * N_NODES) g_pack[i] = 0ull;
    } else {
        __shared__ float sW[XD * HD];
        for (int i = threadIdx.x; i < XD * HD; i += blockDim.x) sW[i] = W1[i];
        __syncthreads();
        int node = (bx - NB_INI) * 8 + (threadIdx.x >> 5);
        int lane = threadIdx.x & 31;
        if (node >= N_NODES) return;
        xw1_work(x, sW, node, lane);
    }
}

__global__ void k_bin01(const int* __restrict__ ei, const float* __restrict__ ew) {
    int idx = blockIdx.x * blockDim.x + threadIdx.x;   // 2*E threads
    if (idx >= 2 * E_EDGES) return;
    int t = idx < E_EDGES ? 0 : 1;
    int e = idx - t * E_EDGES;
    bin_work(t, e, ei, ew);
}

__global__ void k_dinv0() {
    int i = blockIdx.x * blockDim.x + threadIdx.x;
    if (i < N_NODES) dinv_work(i);
}

// ============================================================
// Pipelined step kernel (proven role order):
//   [0, NB_L)                layer1(t)    -> z_w
//   [NB_L, 2*NB_L)           layer2(t-1)  (if t >= 1)
//   [2*NB_L, +NB_BIN)        bin(t+2)     (if t+2 < T)
//   [2*NB_L+NB_BIN, +NB_DNV) dinv(t+1)    (if t+1 < T)
// ============================================================
__global__ void k_step(const float* __restrict__ b1, const float* __restrict__ W2,
                       const float* __restrict__ b2,
                       float* __restrict__ out_prev, int t,
                       const __half* __restrict__ z_r, __half* __restrict__ z_w,
                       const int* __restrict__ ei, const float* __restrict__ ew) {
    int bx = blockIdx.x;
    int lane = threadIdx.x & 31;

    if (bx < NB_L) {
        __shared__ float2 sW2p[32 * 32];   // packed W2 pairs (8 KB)
        for (int i = threadIdx.x; i < 32 * 32; i += blockDim.x) {
            int k = i >> 5, j = i & 31;
            sW2p[i] = make_float2(W2[(2 * k) * ZD + j], W2[(2 * k + 1) * ZD + j]);
        }
        __syncthreads();
        int node = bx * 8 + (threadIdx.x >> 5);
        if (node >= N_NODES) return;
        layer1_work(b1, sW2p, t, z_w, node, lane);
    } else if (bx < 2 * NB_L) {
        if (t == 0) return;
        int node = (bx - NB_L) * 8 + (threadIdx.x >> 5);
        if (node >= N_NODES) return;
        layer2_work(b2, z_r, out_prev, t - 1, node, lane);
    } else if (bx < 2 * NB_L + NB_BIN) {
        int tb = t + 2;
        if (tb >= T_STEPS) return;
        int e = (bx - 2 * NB_L) * 256 + threadIdx.x;
        if (e < E_EDGES) bin_work(tb, e, ei, ew);
    } else {
        int td = t + 1;
        if (td >= T_STEPS) return;
        int i = (bx - 2 * NB_L - NB_BIN) * 256 + threadIdx.x;
        if (i < N_NODES) dinv_work(td * N_NODES + i);
    }
}

__global__ void k_layer2_last(const float* __restrict__ b2, float* __restrict__ out_t,
                              const __half* __restrict__ zbuf) {
    int node = blockIdx.x * (blockDim.x >> 5) + (threadIdx.x >> 5);
    int lane = threadIdx.x & 31;
    if (node >= N_NODES) return;
    layer2_work(b2, zbuf, out_t, T_STEPS - 1, node, lane);
}

// ============================================================
// Launch
// ============================================================
extern "C" void kernel_launch(void* const* d_in, const int* in_sizes, int n_in,
                              void* d_out, int out_size) {
    const float* x  = (const float*)d_in[0];   // [N, 128]
    const int*   ei = (const int*)d_in[1];     // [T, 2, E]
    const float* ew = (const float*)d_in[2];   // [T, E]
    const float* W1 = (const float*)d_in[3];   // [128, 64]
    const float* b1 = (const float*)d_in[4];   // [64]
    const float* W2 = (const float*)d_in[5];   // [64, 32]
    const float* b2 = (const float*)d_in[6];   // [32]
    float* out = (float*)d_out;                // [T, N, 32]

    const int B = 256;

    __half* z0; __half* z1;
    cudaGetSymbolAddress((void**)&z0, g_hW2);
    z1 = z0 + (size_t)N_NODES * ZD;

    // prologue
    k_prologA<<<NB_INI + NB_L, B>>>(x, W1);
    k_bin01<<<(2 * E_EDGES + B - 1) / B, B>>>(ei, ew);
    k_dinv0<<<(N_NODES + B - 1) / B, B>>>();

    // pipelined steps
    const int GRID = 2 * NB_L + NB_BIN + NB_DNV;
    for (int t = 0; t < T_STEPS; t++) {
        float* out_prev = out + (size_t)(t - 1) * N_NODES * ZD;  // unused at t=0
        __half* z_r = (t & 1) ? z0 : z1;
        __half* z_w = (t & 1) ? z1 : z0;
        k_step<<<GRID, B>>>(b1, W2, b2, out_prev, t, z_r, z_w, ei, ew);
    }

    // epilogue: layer2 for t = 7
    k_layer2_last<<<NB_L, B>>>(b2, out + (size_t)(T_STEPS - 1) * N_NODES * ZD,
                               ((T_STEPS - 1) & 1) ? z1 : z0);
}

// round 17
// speedup vs baseline: 1.3043x; 1.0109x over previous
#include <cuda_runtime.h>
#include <cuda_fp16.h>

#define N_NODES 50000
#define T_STEPS 8
#define E_EDGES 800000
#define XD 128
#define HD 64
#define ZD 32
#define CAP 96       // Poisson(16) tail beyond 96 ~ e^-80

#define NB_L   6250  // layer role blocks: 50000 nodes / 8 warps per block
#define NB_BIN 3125  // bin role blocks: 800000 edges / 256
#define NB_DNV 196   // dinv role blocks: 50000 / 256
#define NB_INI 1563  // init role blocks: 400000 / 256

// ---- scratch (no allocations allowed) ----
__device__ __half g_xW1[N_NODES * HD];                      // x @ W1, fp16 (6.4 MB)
__device__ __half g_hW2[2][N_NODES * ZD];                   // z = h@W2, fp16, dbl-buffered
__device__ unsigned long long g_pack[T_STEPS * N_NODES];    // (count<<52)|fixed32(sum w)
__device__ float  g_dinv[T_STEPS * N_NODES];
__device__ int    g_count[T_STEPS * N_NODES];
__device__ unsigned g_bins[(size_t)T_STEPS * N_NODES * CAP]; // packed (s, fp16 w|nrm) (154 MB)

// pack helpers: low 16 bits = src node (< 65536), high 16 bits = fp16 payload
__device__ __forceinline__ unsigned pack_sn(int s, float v) {
    return (unsigned)s | ((unsigned)__half_as_ushort(__float2half(v)) << 16);
}
__device__ __forceinline__ int   up_s(unsigned p)   { return (int)(p & 0xFFFFu); }
__device__ __forceinline__ float up_n(unsigned p)   {
    return __half2float(__ushort_as_half((unsigned short)(p >> 16)));
}

// bit casts (no intrinsic for half2<->uint in this toolkit)
__device__ __forceinline__ unsigned h2_as_u(__half2 v) {
    unsigned u; *reinterpret_cast<__half2*>(&u) = v; return u;
}
__device__ __forceinline__ __half2 u_as_h2(unsigned u) {
    return *reinterpret_cast<__half2*>(&u);
}

// ============================================================
// Work bodies
// ============================================================
__device__ __forceinline__ void xw1_work(const float* __restrict__ x,
                                         const float* sW, int node, int lane) {
    const float* xr = x + node * XD;
    float xv[4];
    xv[0] = xr[lane];
    xv[1] = xr[lane + 32];
    xv[2] = xr[lane + 64];
    xv[3] = xr[lane + 96];

    float a0 = 0.f, a1 = 0.f;
#pragma unroll
    for (int q = 0; q < 4; q++) {
#pragma unroll
        for (int k = 0; k < 32; k++) {
            float xk = __shfl_sync(0xffffffffu, xv[q], k);
            int kk = q * 32 + k;
            a0 = fmaf(xk, sW[kk * HD + lane], a0);
            a1 = fmaf(xk, sW[kk * HD + lane + 32], a1);
        }
    }
    g_xW1[node * HD + lane]      = __float2half(a0);
    g_xW1[node * HD + lane + 32] = __float2half(a1);
}

__device__ __forceinline__ void bin_work(int t, int e, const int* __restrict__ ei,
                                         const float* __restrict__ ew) {
    const int* src = ei + (size_t)t * 2 * E_EDGES;
    const int* dst = src + E_EDGES;
    int s = src[e];
    int d = dst[e];
    float w = ew[(size_t)t * E_EDGES + e];
    int base = t * N_NODES + d;
    unsigned long long add =
        (1ull << 52) | (unsigned long long)(w * 4294967296.0f);
    unsigned long long old = atomicAdd(&g_pack[base], add);
    int p = (int)(old >> 52);
    if (p < CAP) g_bins[(size_t)base * CAP + p] = pack_sn(s, w);  // 4B packed
}

__device__ __forceinline__ void dinv_work(int i) {
    unsigned long long v = g_pack[i];
    g_count[i] = (int)(v >> 52);
    float deg = 1.0f + (float)(v & ((1ull << 52) - 1ull)) * (1.0f / 4294967296.0f);
    g_dinv[i] = rsqrtf(deg);
}

// layer1: gather(xW1 fp16) + b1 + relu + (h @ W2) -> z (fp16)
// Gather: 1 SHFL/neighbor (packed).  Tail: 32 SHFL + 16 LDS.128 + 64 FMA.
// sW2q[k4*32 + lane] = (W2[4k4][lane], W2[4k4+1][lane], W2[4k4+2][lane], W2[4k4+3][lane])
__device__ __forceinline__ void layer1_work(const float* __restrict__ b1,
                                            const float4* sW2q, int t,
                                            __half* __restrict__ zbuf,
                                            int node, int lane) {
    int base = t * N_NODES + node;
    float dv = g_dinv[base];
    int   c  = min(g_count[base], CAP);
    const float* dinv_t = g_dinv + t * N_NODES;
    unsigned* bp = g_bins + (size_t)base * CAP;

    // coalesced prefetch: lane handles entries lane, +32, +64; repack (s, nrm)
    unsigned pj[3];
#pragma unroll
    for (int r = 0; r < 3; r++) {
        int j = lane + 32 * r;
        pj[r] = 0u;
        if (j < c) {
            unsigned ent = bp[j];
            int   s = up_s(ent);
            float w = up_n(ent);
            float nrm = dinv_t[s] * w * dv;
            unsigned p = pack_sn(s, nrm);
            pj[r] = p;
            bp[j] = p;                      // layer 2 reuses packed (s, nrm)
        }
    }

    const __half2* xw = reinterpret_cast<const __half2*>(g_xW1);

    float2 me = __half22float2(xw[node * 32 + lane]);   // self-loop, norm = dv*dv
    float accx = me.x * (dv * dv);
    float accy = me.y * (dv * dv);

#pragma unroll
    for (int r = 0; r < 3; r++) {
        int cnt = min(max(c - 32 * r, 0), 32);
#pragma unroll 8
        for (int k = 0; k < cnt; k++) {
            unsigned p = __shfl_sync(0xffffffffu, pj[r], k);   // ONE shfl
            int   s   = up_s(p);
            float nrm = up_n(p);
            float2 v = __half22float2(xw[s * 32 + lane]);      // 128B coalesced row
            accx = fmaf(v.x, nrm, accx);
            accy = fmaf(v.y, nrm, accy);
        }
    }

    float2 bb = reinterpret_cast<const float2*>(b1)[lane];
    float h0 = fmaxf(accx + bb.x, 0.0f);   // h[2*lane]
    float h1 = fmaxf(accy + bb.y, 0.0f);   // h[2*lane+1]

    // pack h pair -> half2; tail = 32 SHFL + 16 LDS.128 + 64 FMA (fp32 accum)
    unsigned hp = h2_as_u(__floats2half2_rn(h0, h1));
    float z0 = 0.f, z1 = 0.f;
#pragma unroll
    for (int k4 = 0; k4 < 16; k4++) {
        unsigned pa = __shfl_sync(0xffffffffu, hp, 2 * k4);       // h[4k4], h[4k4+1]
        unsigned pb = __shfl_sync(0xffffffffu, hp, 2 * k4 + 1);   // h[4k4+2], h[4k4+3]
        float4 wq = sW2q[k4 * 32 + lane];                          // conflict-free LDS.128
        float2 ha = __half22float2(u_as_h2(pa));
        float2 hb = __half22float2(u_as_h2(pb));
        z0 = fmaf(ha.x, wq.x, z0);
        z0 = fmaf(ha.y, wq.y, z0);
        z1 = fmaf(hb.x, wq.z, z1);
        z1 = fmaf(hb.y, wq.w, z1);
    }
    zbuf[node * ZD + lane] = __float2half(z0 + z1);
}

// layer2: gather(z fp16) + b2 + tanh -> out_t  (bins hold packed (s, nrm))
__device__ __forceinline__ void layer2_work(const float* __restrict__ b2,
                                            const __half* __restrict__ zbuf,
                                            float* __restrict__ out_t, int t,
                                            int node, int lane) {
    int base = t * N_NODES + node;
    float dv = g_dinv[base];
    int   c  = min(g_count[base], CAP);
    const unsigned* bp = g_bins + (size_t)base * CAP;

    unsigned pj[3];
#pragma unroll
    for (int r = 0; r < 3; r++) {
        int j = lane + 32 * r;
        pj[r] = 0u;
        if (j < c) pj[r] = bp[j];           // packed (s, nrm)
    }

    float acc = __half2float(zbuf[node * ZD + lane]) * (dv * dv);

#pragma unroll
    for (int r = 0; r < 3; r++) {
        int cnt = min(max(c - 32 * r, 0), 32);
#pragma unroll 8
        for (int k = 0; k < cnt; k++) {
            unsigned p = __shfl_sync(0xffffffffu, pj[r], k);   // ONE shfl
            int   s   = up_s(p);
            float nrm = up_n(p);
            acc = fmaf(__half2float(zbuf[s * ZD + lane]), nrm, acc);  // 64B rows
        }
    }
    out_t[node * ZD + lane] = tanhf(acc + b2[lane]);
}

// ============================================================
// Fused prologue A: init role + xw1 role
// ============================================================
__global__ void k_prologA(const float* __restrict__ x, const float* __restrict__ W1) {
    int bx = blockIdx.x;
    if (bx < NB_INI) {
        int i = bx * 256 + threadIdx.x;
        if (i < T_STEPS * N_NODES) g_pack[i] = 0ull;
    } else {
        __shared__ float sW[XD * HD];
        for (int i = threadIdx.x; i < XD * HD; i += blockDim.x) sW[i] = W1[i];
        __syncthreads();
        int node = (bx - NB_INI) * 8 + (threadIdx.x >> 5);
        int lane = threadIdx.x & 31;
        if (node >= N_NODES) return;
        xw1_work(x, sW, node, lane);
    }
}

__global__ void k_bin01(const int* __restrict__ ei, const float* __restrict__ ew) {
    int idx = blockIdx.x * blockDim.x + threadIdx.x;   // 2*E threads
    if (idx >= 2 * E_EDGES) return;
    int t = idx < E_EDGES ? 0 : 1;
    int e = idx - t * E_EDGES;
    bin_work(t, e, ei, ew);
}

__global__ void k_dinv0() {
    int i = blockIdx.x * blockDim.x + threadIdx.x;
    if (i < N_NODES) dinv_work(i);
}

// ============================================================
// Pipelined step kernel (proven role order):
//   [0, NB_L)                layer1(t)    -> z_w
//   [NB_L, 2*NB_L)           layer2(t-1)  (if t >= 1)
//   [2*NB_L, +NB_BIN)        bin(t+2)     (if t+2 < T)
//   [2*NB_L+NB_BIN, +NB_DNV) dinv(t+1)    (if t+1 < T)
// ============================================================
__global__ void k_step(const float* __restrict__ b1, const float* __restrict__ W2,
                       const float* __restrict__ b2,
                       float* __restrict__ out_prev, int t,
                       const __half* __restrict__ z_r, __half* __restrict__ z_w,
                       const int* __restrict__ ei, const float* __restrict__ ew) {
    int bx = blockIdx.x;
    int lane = threadIdx.x & 31;

    if (bx < NB_L) {
        __shared__ float4 sW2q[16 * 32];   // packed W2 quads (8 KB)
        for (int i = threadIdx.x; i < 16 * 32; i += blockDim.x) {
            int k4 = i >> 5, j = i & 31;
            sW2q[i] = make_float4(W2[(4 * k4) * ZD + j], W2[(4 * k4 + 1) * ZD + j],
                                  W2[(4 * k4 + 2) * ZD + j], W2[(4 * k4 + 3) * ZD + j]);
        }
        __syncthreads();
        int node = bx * 8 + (threadIdx.x >> 5);
        if (node >= N_NODES) return;
        layer1_work(b1, sW2q, t, z_w, node, lane);
    } else if (bx < 2 * NB_L) {
        if (t == 0) return;
        int node = (bx - NB_L) * 8 + (threadIdx.x >> 5);
        if (node >= N_NODES) return;
        layer2_work(b2, z_r, out_prev, t - 1, node, lane);
    } else if (bx < 2 * NB_L + NB_BIN) {
        int tb = t + 2;
        if (tb >= T_STEPS) return;
        int e = (bx - 2 * NB_L) * 256 + threadIdx.x;
        if (e < E_EDGES) bin_work(tb, e, ei, ew);
    } else {
        int td = t + 1;
        if (td >= T_STEPS) return;
        int i = (bx - 2 * NB_L - NB_BIN) * 256 + threadIdx.x;
        if (i < N_NODES) dinv_work(td * N_NODES + i);
    }
}

__global__ void k_layer2_last(const float* __restrict__ b2, float* __restrict__ out_t,
                              const __half* __restrict__ zbuf) {
    int node = blockIdx.x * (blockDim.x >> 5) + (threadIdx.x >> 5);
    int lane = threadIdx.x & 31;
    if (node >= N_NODES) return;
    layer2_work(b2, zbuf, out_t, T_STEPS - 1, node, lane);
}

// ============================================================
// Launch
// ============================================================
extern "C" void kernel_launch(void* const* d_in, const int* in_sizes, int n_in,
                              void* d_out, int out_size) {
    const float* x  = (const float*)d_in[0];   // [N, 128]
    const int*   ei = (const int*)d_in[1];     // [T, 2, E]
    const float* ew = (const float*)d_in[2];   // [T, E]
    const float* W1 = (const float*)d_in[3];   // [128, 64]
    const float* b1 = (const float*)d_in[4];   // [64]
    const float* W2 = (const float*)d_in[5];   // [64, 32]
    const float* b2 = (const float*)d_in[6];   // [32]
    float* out = (float*)d_out;                // [T, N, 32]

    const int B = 256;

    __half* z0; __half* z1;
    cudaGetSymbolAddress((void**)&z0, g_hW2);
    z1 = z0 + (size_t)N_NODES * ZD;

    // prologue
    k_prologA<<<NB_INI + NB_L, B>>>(x, W1);
    k_bin01<<<(2 * E_EDGES + B - 1) / B, B>>>(ei, ew);
    k_dinv0<<<(N_NODES + B - 1) / B, B>>>();

    // pipelined steps
    const int GRID = 2 * NB_L + NB_BIN + NB_DNV;
    for (int t = 0; t < T_STEPS; t++) {
        float* out_prev = out + (size_t)(t - 1) * N_NODES * ZD;  // unused at t=0
        __half* z_r = (t & 1) ? z0 : z1;
        __half* z_w = (t & 1) ? z1 : z0;
        k_step<<<GRID, B>>>(b1, W2, b2, out_prev, t, z_r, z_w, ei, ew);
    }

    // epilogue: layer2 for t = 7
    k_layer2_last<<<NB_L, B>>>(b2, out + (size_t)(T_STEPS - 1) * N_NODES * ZD,
                               ((T_STEPS - 1) & 1) ? z1 : z0);
}